// round 9
// baseline (speedup 1.0000x reference)
#include <cuda_runtime.h>
#include <math.h>

// Problem shape (fixed per reference): h is (32, 4096, 1024) fp32.
#define BATCH   32
#define SEQ     4096
#define HID     1024
#define W       32          // window rows
#define WSTART  2032        // 4096/2 - 16
#define NCH     8           // d-chunks
#define CHUNK   128         // HID / NCH
#define NPAIR   528         // 32*33/2 upper-triangle incl diag
#define NTHR    544         // 17 warps
#define FULLM   0xFFFFFFFFu

// ---------------------------------------------------------------------------
// Helpers
// ---------------------------------------------------------------------------
__device__ __forceinline__ float wmin32(float v) {
    #pragma unroll
    for (int o = 16; o; o >>= 1) v = fminf(v, __shfl_xor_sync(FULLM, v, o));
    return v;
}
__device__ __forceinline__ float wmax32(float v) {
    #pragma unroll
    for (int o = 16; o; o >>= 1) v = fmaxf(v, __shfl_xor_sync(FULLM, v, o));
    return v;
}

// Dynamic select a[k] (runtime k) from a static register array (one-time use).
__device__ __forceinline__ float sel32(const float (&a)[32], int k) {
    float t16[16], t8[8], t4[4], t2[2];
    #pragma unroll
    for (int j = 0; j < 16; j++) t16[j] = (k & 16) ? a[j + 16] : a[j];
    #pragma unroll
    for (int j = 0; j < 8;  j++) t8[j]  = (k & 8)  ? t16[j + 8] : t16[j];
    #pragma unroll
    for (int j = 0; j < 4;  j++) t4[j]  = (k & 4)  ? t8[j + 4]  : t8[j];
    #pragma unroll
    for (int j = 0; j < 2;  j++) t2[j]  = (k & 2)  ? t4[j + 2]  : t4[j];
    return (k & 1) ? t2[1] : t2[0];
}

// Sturm count for 32x32 tridiagonal (diag dS, squared offdiag e2S): #eigs < x.
__device__ __forceinline__ int sturm32(const float* __restrict__ dS,
                                       const float* __restrict__ e2S, float x) {
    float dp = dS[0] - x;
    int cnt = (dp < 0.f) ? 1 : 0;
    #pragma unroll
    for (int i = 1; i < 32; i++) {
        float den = copysignf(fmaxf(fabsf(dp), 1e-25f), dp);
        dp = (dS[i] - x) - __fdividef(e2S[i - 1], den);
        cnt += (dp < 0.f) ? 1 : 0;
    }
    return cnt;
}

// ---------------------------------------------------------------------------
// Fused kernel: one block per batch (pad grid to 148; extras exit).
// Phase A: double-buffered Gram over 8 x (32x128) tiles, fp64 accumulators.
// Phase B: centering + normalization -> C (fp32) in smem.
// Phase C: warp 0 Householder tridiagonalization (smem dot products; lane k
//          publishes its row MASKED to j>k — stale eliminated entries are
//          O(1), not eps, and must never enter the reflector) + Sturm.
// Shared memory phases alias one 33 KB pool.
// ---------------------------------------------------------------------------
__global__ void __launch_bounds__(NTHR) fused_kernel(const float* __restrict__ h,
                                                     float* __restrict__ out, int n) {
    const int b = blockIdx.x;
    if (b >= BATCH) return;
    const int tid  = threadIdx.x;
    const int lane = tid & 31;
    const int wid  = tid >> 5;

    __shared__ __align__(16) char pool[2 * 32 * 129 * 4];   // 33024 B
    __shared__ double rsum[W];
    __shared__ double Ssum;
    __shared__ double traceSh;
    __shared__ float  dinv[W];

    float (*tile0)[129] = reinterpret_cast<float(*)[129]>(pool);
    float (*tile1)[129] = reinterpret_cast<float(*)[129]>(pool + 16512);
    double (*Gs)[W + 1] = reinterpret_cast<double(*)[W + 1]>(pool);          // 8448 B
    float  (*Abuf)[W + 1] = reinterpret_cast<float(*)[W + 1]>(pool + 8448);  // 4224 B
    float* xSh  = reinterpret_cast<float*>(pool + 12672);   // v buffer (128 B)
    float* pSh  = reinterpret_cast<float*>(pool + 12800);   // p buffer
    float* dS   = reinterpret_cast<float*>(pool + 12928);
    float* e2S  = reinterpret_cast<float*>(pool + 13056);
    float* eaS  = reinterpret_cast<float*>(pool + 13184);

    const float* base = h + ((size_t)b * SEQ + WSTART) * HID;

    // ---- pair decode (once) ----
    int pi = 0, pj = 0;
    if (tid < NPAIR) {
        int i = 0, rem = tid;
        while (rem >= W - i) { rem -= W - i; i++; }
        pi = i; pj = i + rem;
    }

    // ================= Phase A: Gram with double-buffered tiles =============
    for (int idx = tid; idx < 1024; idx += NTHR) {
        int row = idx >> 5, c4 = idx & 31;
        float4 v = *(const float4*)(base + (size_t)row * HID + c4 * 4);
        tile0[row][c4 * 4 + 0] = v.x; tile0[row][c4 * 4 + 1] = v.y;
        tile0[row][c4 * 4 + 2] = v.z; tile0[row][c4 * 4 + 3] = v.w;
    }
    __syncthreads();

    float (*cur)[129] = tile0;
    float (*nxt)[129] = tile1;
    double acc = 0.0;

    #pragma unroll 1
    for (int ch = 0; ch < NCH; ch++) {
        float4 pf0, pf1; int i0 = -1, i1 = -1;
        if (ch < NCH - 1) {
            const float* nb = base + (ch + 1) * CHUNK;
            int idx = tid;
            if (idx < 1024) {
                pf0 = *(const float4*)(nb + (size_t)(idx >> 5) * HID + (idx & 31) * 4);
                i0 = idx;
            }
            idx = tid + NTHR;
            if (idx < 1024) {
                pf1 = *(const float4*)(nb + (size_t)(idx >> 5) * HID + (idx & 31) * 4);
                i1 = idx;
            }
        }
        if (tid < NPAIR) {
            const float* ai = cur[pi];
            const float* aj = cur[pj];
            float a0 = 0.f, a1 = 0.f, a2 = 0.f, a3 = 0.f;
            #pragma unroll
            for (int d = 0; d < CHUNK; d += 4) {
                a0 = fmaf(ai[d + 0], aj[d + 0], a0);
                a1 = fmaf(ai[d + 1], aj[d + 1], a1);
                a2 = fmaf(ai[d + 2], aj[d + 2], a2);
                a3 = fmaf(ai[d + 3], aj[d + 3], a3);
            }
            acc += (double)((a0 + a1) + (a2 + a3));
        }
        if (i0 >= 0) {
            int row = i0 >> 5, c4 = i0 & 31;
            nxt[row][c4 * 4 + 0] = pf0.x; nxt[row][c4 * 4 + 1] = pf0.y;
            nxt[row][c4 * 4 + 2] = pf0.z; nxt[row][c4 * 4 + 3] = pf0.w;
        }
        if (i1 >= 0) {
            int row = i1 >> 5, c4 = i1 & 31;
            nxt[row][c4 * 4 + 0] = pf1.x; nxt[row][c4 * 4 + 1] = pf1.y;
            nxt[row][c4 * 4 + 2] = pf1.z; nxt[row][c4 * 4 + 3] = pf1.w;
        }
        __syncthreads();
        float (*t)[129] = cur; cur = nxt; nxt = t;
    }

    // tiles dead; write symmetric Gram (Gs aliases tile0 region)
    if (tid < NPAIR) {
        Gs[pi][pj] = acc;
        Gs[pj][pi] = acc;
    }
    __syncthreads();

    // ================= Phase B: centering + normalization ===================
    if (tid < W) {
        double r = 0.0;
        #pragma unroll
        for (int j = 0; j < W; j++) r += Gs[tid][j];
        rsum[tid] = r;
    }
    __syncthreads();
    if (tid == 0) {
        double s = 0.0;
        #pragma unroll
        for (int i = 0; i < W; i++) s += rsum[i];
        Ssum = s;
    }
    __syncthreads();

    const double Sq = Ssum * (1.0 / 1024.0);   // S / 32^2

    if (tid < W) {
        double di = Gs[tid][tid] - rsum[tid] * (1.0 / 16.0) + Sq;
        if (di < 0.0) di = 0.0;
        dinv[tid] = (float)(1.0 / (sqrt(di) + 1e-8));
    }
    __syncthreads();

    #pragma unroll
    for (int e = 0; e < 2; e++) {
        int idx = tid + e * NTHR;
        if (idx < W * W) {
            int k = idx >> 5, l = idx & 31;
            double gc = Gs[k][l] - rsum[k] * (1.0 / 32.0) - rsum[l] * (1.0 / 32.0) + Sq;
            Abuf[k][l] = (float)gc * dinv[k] * dinv[l];
        }
    }
    __syncthreads();
    if (tid == 0) {
        double tr = 0.0;
        #pragma unroll
        for (int i = 0; i < W; i++) tr += (double)Abuf[i][i];
        traceSh = tr;
    }
    __syncthreads();

    if (wid != 0) return;   // warps 1..16 retire; warp 0 owns the eigensolve

    // ================= Phase C1: Householder tridiagonalization =============
    // Lane i holds row i in registers. Column k == row k (symmetry); lane k
    // publishes its row MASKED to entries j > k. (Entries j <= k hold stale
    // O(1) eliminated values - the masked rank-2 update never zeroes them -
    // so they MUST NOT enter sigma/p.)
    float a[32];
    #pragma unroll
    for (int j = 0; j < 32; j++) a[j] = Abuf[lane][j];

    const float4* x4 = reinterpret_cast<const float4*>(xSh);
    const float4* p4 = reinterpret_cast<const float4*>(pSh);

    #pragma unroll 1
    for (int k = 0; k < 30; k++) {
        const int m = k + 1;
        if (lane == k) {
            float4* w4 = reinterpret_cast<float4*>(xSh);
            #pragma unroll
            for (int c = 0; c < 8; c++) {
                w4[c] = make_float4(
                    (4 * c + 0 > k) ? a[4 * c + 0] : 0.f,
                    (4 * c + 1 > k) ? a[4 * c + 1] : 0.f,
                    (4 * c + 2 > k) ? a[4 * c + 2] : 0.f,
                    (4 * c + 3 > k) ? a[4 * c + 3] : 0.f);
            }
        }
        __syncwarp();

        // sigma = |x|^2 (local dot; entries <= k are zero)
        float s0 = 0.f, s1 = 0.f, s2 = 0.f, s3 = 0.f;
        #pragma unroll
        for (int c = 0; c < 8; c++) {
            float4 v = x4[c];
            s0 = fmaf(v.x, v.x, s0); s1 = fmaf(v.y, v.y, s1);
            s2 = fmaf(v.z, v.z, s2); s3 = fmaf(v.w, v.w, s3);
        }
        float sig = (s0 + s1) + (s2 + s3);
        float x0  = xSh[m];
        float nrm = sqrtf(sig);
        float alpha = -copysignf(nrm, x0);
        float beta  = (sig > 1e-30f) ? __fdividef(1.f, sig + fabsf(x0) * nrm) : 0.f;
        __syncwarp();
        if (lane == m) xSh[m] = x0 - alpha;
        __syncwarp();

        float vi = (lane >= m) ? ((lane == m) ? x0 - alpha : xSh[lane]) : 0.f;

        // p = beta * (A v); v_j = 0 for j <= k masks stale row entries
        float q0 = 0.f, q1 = 0.f, q2 = 0.f, q3 = 0.f;
        #pragma unroll
        for (int c = 0; c < 8; c++) {
            float4 v = x4[c];
            q0 = fmaf(a[4 * c + 0], v.x, q0);
            q1 = fmaf(a[4 * c + 1], v.y, q1);
            q2 = fmaf(a[4 * c + 2], v.z, q2);
            q3 = fmaf(a[4 * c + 3], v.w, q3);
        }
        float p = ((q0 + q1) + (q2 + q3));
        p = (lane >= m) ? p * beta : 0.f;
        pSh[lane] = p;
        __syncwarp();

        // vtp = v . p (local dot)
        float t0 = 0.f, t1 = 0.f, t2 = 0.f, t3 = 0.f;
        #pragma unroll
        for (int c = 0; c < 8; c++) {
            float4 vv = x4[c];
            float4 pp = p4[c];
            t0 = fmaf(vv.x, pp.x, t0); t1 = fmaf(vv.y, pp.y, t1);
            t2 = fmaf(vv.z, pp.z, t2); t3 = fmaf(vv.w, pp.w, t3);
        }
        float vtp = (t0 + t1) + (t2 + t3);
        float Kc  = 0.5f * beta * vtp;
        float qi  = p - Kc * vi;

        // A -= v q^T + q v^T  with q_j = p_j - Kc*v_j computed on the fly
        #pragma unroll
        for (int c = 0; c < 8; c++) {
            float4 vv = x4[c];
            float4 pp = p4[c];
            float qx = fmaf(-Kc, vv.x, pp.x);
            float qy = fmaf(-Kc, vv.y, pp.y);
            float qz = fmaf(-Kc, vv.z, pp.z);
            float qw = fmaf(-Kc, vv.w, pp.w);
            a[4 * c + 0] = fmaf(-vi, qx, fmaf(-qi, vv.x, a[4 * c + 0]));
            a[4 * c + 1] = fmaf(-vi, qy, fmaf(-qi, vv.y, a[4 * c + 1]));
            a[4 * c + 2] = fmaf(-vi, qz, fmaf(-qi, vv.z, a[4 * c + 2]));
            a[4 * c + 3] = fmaf(-vi, qw, fmaf(-qi, vv.w, a[4 * c + 3]));
        }
        __syncwarp();   // xSh/pSh reused next iteration

        if (lane == 0) { e2S[k] = alpha * alpha; eaS[k] = fabsf(alpha); }
    }
    {   // last offdiagonal e_30 = A[30][31]
        float e30 = __shfl_sync(FULLM, a[31], 30);
        if (lane == 0) {
            e2S[30] = e30 * e30; eaS[30] = fabsf(e30);
            e2S[31] = 0.f;       eaS[31] = 0.f;
        }
    }
    dS[lane] = sel32(a, lane);   // diagonal
    __syncwarp();

    // ================= Phase C2: multi-point Sturm bisection ================
    float eprev = (lane > 0) ? eaS[lane - 1] : 0.f;
    float rad   = eaS[lane] + eprev;
    float lo = wmin32(dS[lane] - rad);
    float hi = wmax32(dS[lane] + rad);

    // 3 targets x 10 lanes: ascending eigen indices 31 (e0), 24 (e7), 23 (e8).
    int g = lane / 10; if (g > 2) g = 2;
    const int m = lane - g * 10;                 // 0..9 (lanes 30,31 ignored)
    const int idx = (g == 0) ? 31 : (g == 1) ? 24 : 23;

    #pragma unroll 1
    for (int r = 0; r < 8; r++) {
        float w  = (hi - lo) * (1.0f / 11.0f);
        float xx = lo + w * (float)(m + 1);
        int   cnt  = sturm32(dS, e2S, xx);
        unsigned bal = __ballot_sync(FULLM, cnt <= idx);   // x left of lambda_idx
        unsigned gb  = (bal >> (g * 10)) & 0x3FFu;
        int mstar = 31 - __clz(gb);                        // -1..9
        lo = lo + w * (float)(mstar + 1);
        hi = lo + w;
    }
    float lam = 0.5f * (lo + hi);
    float e0 = __shfl_sync(FULLM, lam, 0);
    float e7 = __shfl_sync(FULLM, lam, 10);
    float e8 = __shfl_sync(FULLM, lam, 20);

    if (lane == 0) {
        float gap   = e7 - e8;
        float decay = (e0 - e8) * (1.0f / 9.0f);
        float lmin  = e8 + 1e-8f;
        float topo  = gap / (decay + 1e-8f);
        if (topo < 0.f) topo = 0.f;
        float geo   = lmin / ((float)traceSh + 1e-8f);
        float gcve  = topo + geo;
        out[b]         = gcve;   // gcve_scores
        out[n + b]     = 0.0f;   // fracture_scores
        out[2 * n + b] = gcve;   // total_pressure
    }
}

// ---------------------------------------------------------------------------
extern "C" void kernel_launch(void* const* d_in, const int* in_sizes, int n_in,
                              void* d_out, int out_size) {
    const float* h = (const float*)d_in[0];
    float* out = (float*)d_out;
    int n = out_size / 3;   // 32

    fused_kernel<<<148, NTHR>>>(h, out, n);   // blocks >= 32 exit immediately
}

// round 10
// speedup vs baseline: 1.3966x; 1.3966x over previous
#include <cuda_runtime.h>
#include <math.h>

// Problem shape (fixed per reference): h is (32, 4096, 1024) fp32.
#define BATCH   32
#define SEQ     4096
#define HID     1024
#define W       32          // window rows
#define WSTART  2032        // 4096/2 - 16
#define NCH     8           // d-chunks
#define CHUNK   128         // HID / NCH
#define NPAIR   528         // 32*33/2 upper-triangle incl diag
#define FULLM   0xFFFFFFFFu

// Scratch: per-batch, per-chunk partial Gram (upper triangle), fp32.
__device__ float g_part[BATCH][NCH][NPAIR];

// ---------------------------------------------------------------------------
// Kernel 1: partial raw Gram R = W W^T over a 128-column chunk.
// grid = (NCH, BATCH), block = 544. (Proven ~6 us wall at 256 blocks.)
// ---------------------------------------------------------------------------
__global__ void __launch_bounds__(544) gram_kernel(const float* __restrict__ h) {
    const int chunk = blockIdx.x;
    const int b     = blockIdx.y;
    __shared__ float As[W][CHUNK + 1];

    const int tid = threadIdx.x;
    const float* base = h + ((size_t)b * SEQ + WSTART) * HID + (size_t)chunk * CHUNK;

    for (int idx = tid; idx < W * (CHUNK / 4); idx += blockDim.x) {
        int row = idx >> 5;
        int c4  = idx & 31;
        float4 v = *(const float4*)(base + (size_t)row * HID + c4 * 4);
        As[row][c4 * 4 + 0] = v.x;
        As[row][c4 * 4 + 1] = v.y;
        As[row][c4 * 4 + 2] = v.z;
        As[row][c4 * 4 + 3] = v.w;
    }
    __syncthreads();

    if (tid < NPAIR) {
        int i = 0, rem = tid;
        while (rem >= W - i) { rem -= W - i; i++; }
        int j = i + rem;

        const float* ai = As[i];
        const float* aj = As[j];
        float a0 = 0.f, a1 = 0.f, a2 = 0.f, a3 = 0.f;
        #pragma unroll
        for (int d = 0; d < CHUNK; d += 4) {
            a0 = fmaf(ai[d + 0], aj[d + 0], a0);
            a1 = fmaf(ai[d + 1], aj[d + 1], a1);
            a2 = fmaf(ai[d + 2], aj[d + 2], a2);
            a3 = fmaf(ai[d + 3], aj[d + 3], a3);
        }
        g_part[b][chunk][tid] = (a0 + a1) + (a2 + a3);
    }
}

// ---------------------------------------------------------------------------
// Helpers
// ---------------------------------------------------------------------------
__device__ __forceinline__ float wmin32(float v) {
    #pragma unroll
    for (int o = 16; o; o >>= 1) v = fminf(v, __shfl_xor_sync(FULLM, v, o));
    return v;
}
__device__ __forceinline__ float wmax32(float v) {
    #pragma unroll
    for (int o = 16; o; o >>= 1) v = fmaxf(v, __shfl_xor_sync(FULLM, v, o));
    return v;
}

// Dynamic select a[k] (runtime k) from a static register array.
__device__ __forceinline__ float sel32(const float (&a)[32], int k) {
    float t16[16], t8[8], t4[4], t2[2];
    #pragma unroll
    for (int j = 0; j < 16; j++) t16[j] = (k & 16) ? a[j + 16] : a[j];
    #pragma unroll
    for (int j = 0; j < 8;  j++) t8[j]  = (k & 8)  ? t16[j + 8] : t16[j];
    #pragma unroll
    for (int j = 0; j < 4;  j++) t4[j]  = (k & 4)  ? t8[j + 4]  : t8[j];
    #pragma unroll
    for (int j = 0; j < 2;  j++) t2[j]  = (k & 2)  ? t4[j + 2]  : t4[j];
    return (k & 1) ? t2[1] : t2[0];
}

// Sturm count for 32x32 tridiagonal: #eigs < x.
__device__ __forceinline__ int sturm32(const float* __restrict__ dS,
                                       const float* __restrict__ e2S, float x) {
    float dp = dS[0] - x;
    int cnt = (dp < 0.f) ? 1 : 0;
    #pragma unroll
    for (int i = 1; i < 32; i++) {
        float den = copysignf(fmaxf(fabsf(dp), 1e-25f), dp);
        dp = (dS[i] - x) - __fdividef(e2S[i - 1], den);
        cnt += (dp < 0.f) ? 1 : 0;
    }
    return cnt;
}

// ---------------------------------------------------------------------------
// Kernel 2: per-batch — prologue (256 threads): reduce partials (fp64),
// center+normalize to C (fp32). Warp 0: Householder tridiagonalization where
// the PUBLISHING LANE computes sigma/alpha/beta itself and publishes the
// finished v vector + beta (2 syncwarps/step, no cross-lane reductions),
// then multi-point Sturm bisection for lambda 0/7/8.
// ---------------------------------------------------------------------------
__global__ void __launch_bounds__(256) eig_kernel(float* __restrict__ out, int n) {
    const int b = blockIdx.x;
    if (b >= BATCH) return;
    const int tid  = threadIdx.x;
    const int lane = tid & 31;
    const int wid  = tid >> 5;

    __shared__ double Gs[W][W + 1];
    __shared__ double rsum[W];
    __shared__ double Ssum;
    __shared__ double traceSh;
    __shared__ float  dinv[W];
    __shared__ float  Abuf[W][W + 1];
    __shared__ __align__(16) float xSh[W];   // v vector
    __shared__ __align__(16) float pSh[W];   // p vector
    __shared__ float  auxB;                  // beta
    __shared__ float  dS[W];
    __shared__ float  e2S[W];
    __shared__ float  eaS[W];

    // --- reduce chunk partials in double, mirror to full symmetric matrix ---
    for (int t = tid; t < NPAIR; t += 256) {
        double g = 0.0;
        #pragma unroll
        for (int c = 0; c < NCH; c++) g += (double)g_part[b][c][t];
        int i = 0, rem = t;
        while (rem >= W - i) { rem -= W - i; i++; }
        int j = i + rem;
        Gs[i][j] = g;
        Gs[j][i] = g;
    }
    __syncthreads();

    if (tid < W) {
        double r = 0.0;
        #pragma unroll
        for (int j = 0; j < W; j++) r += Gs[tid][j];
        rsum[tid] = r;
    }
    __syncthreads();
    if (tid == 0) {
        double s = 0.0;
        #pragma unroll
        for (int i = 0; i < W; i++) s += rsum[i];
        Ssum = s;
    }
    __syncthreads();

    const double Sq = Ssum * (1.0 / 1024.0);   // S / 32^2

    if (tid < W) {
        double di = Gs[tid][tid] - rsum[tid] * (1.0 / 16.0) + Sq;
        if (di < 0.0) di = 0.0;
        dinv[tid] = (float)(1.0 / (sqrt(di) + 1e-8));
    }
    __syncthreads();

    {
        #pragma unroll
        for (int e = 0; e < 4; e++) {
            int idx = tid + e * 256;
            int k = idx >> 5, l = idx & 31;
            double gc = Gs[k][l] - rsum[k] * (1.0 / 32.0) - rsum[l] * (1.0 / 32.0) + Sq;
            Abuf[k][l] = (float)gc * dinv[k] * dinv[l];
        }
    }
    __syncthreads();
    if (tid == 0) {
        double tr = 0.0;
        #pragma unroll
        for (int i = 0; i < W; i++) tr += (double)Abuf[i][i];
        traceSh = tr;
    }
    __syncthreads();

    if (wid != 0) return;   // warps 1..7 retire; warp 0 owns the eigensolve

    // ================= Householder tridiagonalization =======================
    // Lane i holds row i in registers. At step k, lane k (which owns column k
    // by symmetry) computes sigma/alpha/beta locally and publishes the
    // FINISHED v vector (entries <= k zero, v_m = x0 - alpha) plus beta.
    float a[32];
    #pragma unroll
    for (int j = 0; j < 32; j++) a[j] = Abuf[lane][j];

    const float4* x4 = reinterpret_cast<const float4*>(xSh);
    const float4* p4 = reinterpret_cast<const float4*>(pSh);

    #pragma unroll 1
    for (int k = 0; k < 30; k++) {
        const int m = k + 1;
        if (lane == k) {
            // masked column (== own row), sigma in 4 accumulators
            float4* w4 = reinterpret_cast<float4*>(xSh);
            float s0 = 0.f, s1 = 0.f, s2 = 0.f, s3 = 0.f;
            #pragma unroll
            for (int c = 0; c < 8; c++) {
                float ex = (4 * c + 0 > k) ? a[4 * c + 0] : 0.f;
                float ey = (4 * c + 1 > k) ? a[4 * c + 1] : 0.f;
                float ez = (4 * c + 2 > k) ? a[4 * c + 2] : 0.f;
                float ew = (4 * c + 3 > k) ? a[4 * c + 3] : 0.f;
                s0 = fmaf(ex, ex, s0); s1 = fmaf(ey, ey, s1);
                s2 = fmaf(ez, ez, s2); s3 = fmaf(ew, ew, s3);
                w4[c] = make_float4(ex, ey, ez, ew);
            }
            float sig = (s0 + s1) + (s2 + s3);
            float x0  = sel32(a, m);
            float nrm = sqrtf(sig);
            float alpha = -copysignf(nrm, x0);
            float beta  = (sig > 1e-30f) ? __fdividef(1.f, sig + fabsf(x0) * nrm) : 0.f;
            xSh[m] = x0 - alpha;       // v_m (overwrites x_m)
            auxB   = beta;
            e2S[k] = alpha * alpha;
            eaS[k] = fabsf(alpha);
        }
        __syncwarp();

        const float beta = auxB;
        const float vi   = xSh[lane];      // 0 for lanes <= k automatically

        // v into registers, p = beta*(A v) local dot
        float4 xr[8];
        #pragma unroll
        for (int c = 0; c < 8; c++) xr[c] = x4[c];

        float q0 = 0.f, q1 = 0.f, q2 = 0.f, q3 = 0.f;
        #pragma unroll
        for (int c = 0; c < 8; c++) {
            q0 = fmaf(a[4 * c + 0], xr[c].x, q0);
            q1 = fmaf(a[4 * c + 1], xr[c].y, q1);
            q2 = fmaf(a[4 * c + 2], xr[c].z, q2);
            q3 = fmaf(a[4 * c + 3], xr[c].w, q3);
        }
        float p = ((q0 + q1) + (q2 + q3));
        p = (lane >= m) ? p * beta : 0.f;   // rows < m hold stale entries: mask
        pSh[lane] = p;
        __syncwarp();

        float4 pr[8];
        #pragma unroll
        for (int c = 0; c < 8; c++) pr[c] = p4[c];

        // vtp = v . p (register dot)
        float t0 = 0.f, t1 = 0.f, t2 = 0.f, t3 = 0.f;
        #pragma unroll
        for (int c = 0; c < 8; c++) {
            t0 = fmaf(xr[c].x, pr[c].x, t0); t1 = fmaf(xr[c].y, pr[c].y, t1);
            t2 = fmaf(xr[c].z, pr[c].z, t2); t3 = fmaf(xr[c].w, pr[c].w, t3);
        }
        float vtp = (t0 + t1) + (t2 + t3);
        float Kc  = 0.5f * beta * vtp;
        float qi  = p - Kc * vi;            // 0 for lanes < m -> rows untouched

        // A -= v q^T + q v^T  (all registers)
        #pragma unroll
        for (int c = 0; c < 8; c++) {
            float qx = fmaf(-Kc, xr[c].x, pr[c].x);
            float qy = fmaf(-Kc, xr[c].y, pr[c].y);
            float qz = fmaf(-Kc, xr[c].z, pr[c].z);
            float qw = fmaf(-Kc, xr[c].w, pr[c].w);
            a[4 * c + 0] = fmaf(-vi, qx, fmaf(-qi, xr[c].x, a[4 * c + 0]));
            a[4 * c + 1] = fmaf(-vi, qy, fmaf(-qi, xr[c].y, a[4 * c + 1]));
            a[4 * c + 2] = fmaf(-vi, qz, fmaf(-qi, xr[c].z, a[4 * c + 2]));
            a[4 * c + 3] = fmaf(-vi, qw, fmaf(-qi, xr[c].w, a[4 * c + 3]));
        }
        // no extra sync: next publish (lane k+1) writes xSh only after this
        // iteration's pSh-sync, and all xSh reads completed before that sync.
    }
    {   // last offdiagonal e_30 = A[30][31]
        float e30 = __shfl_sync(FULLM, a[31], 30);
        if (lane == 0) {
            e2S[30] = e30 * e30; eaS[30] = fabsf(e30);
            e2S[31] = 0.f;       eaS[31] = 0.f;
        }
    }
    dS[lane] = sel32(a, lane);   // diagonal
    __syncwarp();

    // ================= multi-point Sturm bisection ==========================
    float eprev = (lane > 0) ? eaS[lane - 1] : 0.f;
    float rad   = eaS[lane] + eprev;
    float lo = wmin32(dS[lane] - rad);
    float hi = wmax32(dS[lane] + rad);

    // 3 targets x 10 lanes: ascending eigen indices 31 (e0), 24 (e7), 23 (e8).
    int g = lane / 10; if (g > 2) g = 2;
    const int mm = lane - g * 10;                // 0..9 (lanes 30,31 ignored)
    const int idx = (g == 0) ? 31 : (g == 1) ? 24 : 23;

    #pragma unroll 1
    for (int r = 0; r < 8; r++) {
        float w  = (hi - lo) * (1.0f / 11.0f);
        float xx = lo + w * (float)(mm + 1);
        int   cnt  = sturm32(dS, e2S, xx);
        unsigned bal = __ballot_sync(FULLM, cnt <= idx);
        unsigned gb  = (bal >> (g * 10)) & 0x3FFu;
        int mstar = 31 - __clz(gb);              // -1..9
        lo = lo + w * (float)(mstar + 1);
        hi = lo + w;
    }
    float lam = 0.5f * (lo + hi);
    float e0 = __shfl_sync(FULLM, lam, 0);
    float e7 = __shfl_sync(FULLM, lam, 10);
    float e8 = __shfl_sync(FULLM, lam, 20);

    if (lane == 0) {
        float gap   = e7 - e8;
        float decay = (e0 - e8) * (1.0f / 9.0f);
        float lmin  = e8 + 1e-8f;
        float topo  = gap / (decay + 1e-8f);
        if (topo < 0.f) topo = 0.f;
        float geo   = lmin / ((float)traceSh + 1e-8f);
        float gcve  = topo + geo;
        out[b]         = gcve;   // gcve_scores
        out[n + b]     = 0.0f;   // fracture_scores
        out[2 * n + b] = gcve;   // total_pressure
    }
}

// ---------------------------------------------------------------------------
extern "C" void kernel_launch(void* const* d_in, const int* in_sizes, int n_in,
                              void* d_out, int out_size) {
    const float* h = (const float*)d_in[0];
    float* out = (float*)d_out;
    int n = out_size / 3;   // 32

    dim3 g1(NCH, BATCH);
    gram_kernel<<<g1, 544>>>(h);
    eig_kernel<<<148, 256>>>(out, n);   // blocks >= 32 exit immediately
}

// round 11
// speedup vs baseline: 1.5391x; 1.1020x over previous
#include <cuda_runtime.h>
#include <math.h>

// Problem shape (fixed per reference): h is (32, 4096, 1024) fp32.
#define BATCH   32
#define SEQ     4096
#define HID     1024
#define W       32          // window rows
#define WSTART  2032        // 4096/2 - 16
#define NCH     8           // d-chunks
#define CHUNK   128         // HID / NCH
#define NPAIR   528         // 32*33/2 upper-triangle incl diag
#define FULLM   0xFFFFFFFFu

// Scratch: per-batch, per-chunk partial Gram (upper triangle), fp32.
__device__ float g_part[BATCH][NCH][NPAIR];

// ---------------------------------------------------------------------------
// Kernel 1: partial raw Gram R = W W^T over a 128-column chunk.
// grid = (NCH, BATCH), block = 544.  (proven)
// ---------------------------------------------------------------------------
__global__ void __launch_bounds__(544) gram_kernel(const float* __restrict__ h) {
    const int chunk = blockIdx.x;
    const int b     = blockIdx.y;
    __shared__ float As[W][CHUNK + 1];

    const int tid = threadIdx.x;
    const float* base = h + ((size_t)b * SEQ + WSTART) * HID + (size_t)chunk * CHUNK;

    for (int idx = tid; idx < W * (CHUNK / 4); idx += blockDim.x) {
        int row = idx >> 5;
        int c4  = idx & 31;
        float4 v = *(const float4*)(base + (size_t)row * HID + c4 * 4);
        As[row][c4 * 4 + 0] = v.x;
        As[row][c4 * 4 + 1] = v.y;
        As[row][c4 * 4 + 2] = v.z;
        As[row][c4 * 4 + 3] = v.w;
    }
    __syncthreads();

    if (tid < NPAIR) {
        int i = 0, rem = tid;
        while (rem >= W - i) { rem -= W - i; i++; }
        int j = i + rem;

        const float* ai = As[i];
        const float* aj = As[j];
        float a0 = 0.f, a1 = 0.f, a2 = 0.f, a3 = 0.f;
        #pragma unroll
        for (int d = 0; d < CHUNK; d += 4) {
            a0 = fmaf(ai[d + 0], aj[d + 0], a0);
            a1 = fmaf(ai[d + 1], aj[d + 1], a1);
            a2 = fmaf(ai[d + 2], aj[d + 2], a2);
            a3 = fmaf(ai[d + 3], aj[d + 3], a3);
        }
        g_part[b][chunk][tid] = (a0 + a1) + (a2 + a3);
    }
}

// ---------------------------------------------------------------------------
// Helpers
// ---------------------------------------------------------------------------
__device__ __forceinline__ float wmin32(float v) {
    #pragma unroll
    for (int o = 16; o; o >>= 1) v = fminf(v, __shfl_xor_sync(FULLM, v, o));
    return v;
}
__device__ __forceinline__ float wmax32(float v) {
    #pragma unroll
    for (int o = 16; o; o >>= 1) v = fmaxf(v, __shfl_xor_sync(FULLM, v, o));
    return v;
}

// Dynamic select a[k] (runtime k) from a static register array (used once).
__device__ __forceinline__ float sel32(const float (&a)[32], int k) {
    float t16[16], t8[8], t4[4], t2[2];
    #pragma unroll
    for (int j = 0; j < 16; j++) t16[j] = (k & 16) ? a[j + 16] : a[j];
    #pragma unroll
    for (int j = 0; j < 8;  j++) t8[j]  = (k & 8)  ? t16[j + 8] : t16[j];
    #pragma unroll
    for (int j = 0; j < 4;  j++) t4[j]  = (k & 4)  ? t8[j + 4]  : t8[j];
    #pragma unroll
    for (int j = 0; j < 2;  j++) t2[j]  = (k & 2)  ? t4[j + 2]  : t4[j];
    return (k & 1) ? t2[1] : t2[0];
}

// Sturm count for 32x32 tridiagonal: #eigs < x.
__device__ __forceinline__ int sturm32(const float* __restrict__ dS,
                                       const float* __restrict__ e2S, float x) {
    float dp = dS[0] - x;
    int cnt = (dp < 0.f) ? 1 : 0;
    #pragma unroll
    for (int i = 1; i < 32; i++) {
        float den = copysignf(fmaxf(fabsf(dp), 1e-25f), dp);
        dp = (dS[i] - x) - __fdividef(e2S[i - 1], den);
        cnt += (dp < 0.f) ? 1 : 0;
    }
    return cnt;
}

// ---------------------------------------------------------------------------
// Kernel 2: per-batch. ALL-FP32 prologue (544 threads, one pass over pairs):
// reduce partials, center+normalize -> C. Warp 0: Householder tridiag where
// lane k does ONLY the masked row publish (~145 cyc serial); sigma/alpha/beta
// are computed redundantly by all lanes in parallel from smem. Then
// multi-point Sturm bisection for lambda 0/7/8.
// ---------------------------------------------------------------------------
__global__ void __launch_bounds__(544) eig_kernel(float* __restrict__ out, int n) {
    const int b = blockIdx.x;
    if (b >= BATCH) return;
    const int tid  = threadIdx.x;
    const int lane = tid & 31;
    const int wid  = tid >> 5;

    __shared__ float  Gs[W][W + 1];
    __shared__ float  rsum[W];
    __shared__ float  Ssum;
    __shared__ float  traceSh;
    __shared__ float  dinv[W];
    __shared__ float  Abuf[W][W + 1];
    __shared__ __align__(16) float xSh[W];   // v vector
    __shared__ __align__(16) float pSh[W];   // p vector
    __shared__ float  dS[W];
    __shared__ float  e2S[W];
    __shared__ float  eaS[W];

    // --- reduce chunk partials (fp32), mirror to full symmetric matrix ---
    if (tid < NPAIR) {
        float g = 0.f;
        #pragma unroll
        for (int c = 0; c < NCH; c++) g += g_part[b][c][tid];
        int i = 0, rem = tid;
        while (rem >= W - i) { rem -= W - i; i++; }
        int j = i + rem;
        Gs[i][j] = g;
        Gs[j][i] = g;
    }
    __syncthreads();

    if (tid < W) {
        float r0 = 0.f, r1 = 0.f, r2 = 0.f, r3 = 0.f;
        #pragma unroll
        for (int j = 0; j < W; j += 4) {
            r0 += Gs[tid][j + 0]; r1 += Gs[tid][j + 1];
            r2 += Gs[tid][j + 2]; r3 += Gs[tid][j + 3];
        }
        rsum[tid] = (r0 + r1) + (r2 + r3);
    }
    __syncthreads();
    if (tid == 0) {
        float s0 = 0.f, s1 = 0.f, s2 = 0.f, s3 = 0.f;
        #pragma unroll
        for (int i = 0; i < W; i += 4) {
            s0 += rsum[i + 0]; s1 += rsum[i + 1];
            s2 += rsum[i + 2]; s3 += rsum[i + 3];
        }
        Ssum = (s0 + s1) + (s2 + s3);
    }
    __syncthreads();

    const float Sq = Ssum * (1.0f / 1024.0f);   // S / 32^2

    if (tid < W) {
        float di = Gs[tid][tid] - rsum[tid] * (1.0f / 16.0f) + Sq;
        if (di < 0.f) di = 0.f;
        dinv[tid] = __fdividef(1.f, sqrtf(di) + 1e-8f);
    }
    __syncthreads();

    #pragma unroll
    for (int e = 0; e < 2; e++) {
        int idx = tid + e * 544;
        if (idx < W * W) {
            int k = idx >> 5, l = idx & 31;
            float gc = Gs[k][l] - (rsum[k] + rsum[l]) * (1.0f / 32.0f) + Sq;
            Abuf[k][l] = gc * dinv[k] * dinv[l];
        }
    }
    __syncthreads();
    if (tid == 0) {
        float t0 = 0.f, t1 = 0.f, t2 = 0.f, t3 = 0.f;
        #pragma unroll
        for (int i = 0; i < W; i += 4) {
            t0 += Abuf[i + 0][i + 0]; t1 += Abuf[i + 1][i + 1];
            t2 += Abuf[i + 2][i + 2]; t3 += Abuf[i + 3][i + 3];
        }
        traceSh = (t0 + t1) + (t2 + t3);
    }
    __syncthreads();

    if (wid != 0) return;   // warps 1..16 retire; warp 0 owns the eigensolve

    // ================= Householder tridiagonalization =======================
    // Lane i holds row i in registers. At step k, lane k publishes its row
    // (== column k by symmetry) MASKED to entries > k (8 SELed STS.128,
    // ~145 cyc serial). sigma/x0/alpha/beta are then computed redundantly by
    // ALL lanes in parallel from smem; lane m patches v_m.
    float a[32];
    #pragma unroll
    for (int j = 0; j < 32; j++) a[j] = Abuf[lane][j];

    const float4* x4 = reinterpret_cast<const float4*>(xSh);
    const float4* p4 = reinterpret_cast<const float4*>(pSh);

    #pragma unroll 1
    for (int k = 0; k < 30; k++) {
        const int m = k + 1;
        if (lane == k) {
            float4* w4 = reinterpret_cast<float4*>(xSh);
            #pragma unroll
            for (int c = 0; c < 8; c++) {
                w4[c] = make_float4(
                    (4 * c + 0 > k) ? a[4 * c + 0] : 0.f,
                    (4 * c + 1 > k) ? a[4 * c + 1] : 0.f,
                    (4 * c + 2 > k) ? a[4 * c + 2] : 0.f,
                    (4 * c + 3 > k) ? a[4 * c + 3] : 0.f);
            }
        }
        __syncwarp();

        // ALL lanes: sigma from smem (identical results), alpha, beta
        float s0 = 0.f, s1 = 0.f, s2 = 0.f, s3 = 0.f;
        #pragma unroll
        for (int c = 0; c < 8; c++) {
            float4 v = x4[c];
            s0 = fmaf(v.x, v.x, s0); s1 = fmaf(v.y, v.y, s1);
            s2 = fmaf(v.z, v.z, s2); s3 = fmaf(v.w, v.w, s3);
        }
        float sig = (s0 + s1) + (s2 + s3);
        float x0  = xSh[m];
        float nrm = sqrtf(sig);
        float alpha = -copysignf(nrm, x0);
        float beta  = (sig > 1e-30f) ? __fdividef(1.f, sig + fabsf(x0) * nrm) : 0.f;
        if (lane == k) { e2S[k] = alpha * alpha; eaS[k] = fabsf(alpha); }
        __syncwarp();
        if (lane == m) xSh[m] = x0 - alpha;    // patch v_m
        __syncwarp();

        const float vi = xSh[lane];            // 0 for lanes <= k

        // p = beta * (A v)  (v_j = 0 for j <= k masks stale columns)
        float q0 = 0.f, q1 = 0.f, q2 = 0.f, q3 = 0.f;
        #pragma unroll
        for (int c = 0; c < 8; c++) {
            float4 v = x4[c];
            q0 = fmaf(a[4 * c + 0], v.x, q0);
            q1 = fmaf(a[4 * c + 1], v.y, q1);
            q2 = fmaf(a[4 * c + 2], v.z, q2);
            q3 = fmaf(a[4 * c + 3], v.w, q3);
        }
        float p = ((q0 + q1) + (q2 + q3));
        p = (lane >= m) ? p * beta : 0.f;      // stale rows masked
        pSh[lane] = p;
        __syncwarp();

        // vtp = v . p (redundant local smem dot -> identical Kc)
        float t0 = 0.f, t1 = 0.f, t2 = 0.f, t3 = 0.f;
        #pragma unroll
        for (int c = 0; c < 8; c++) {
            float4 vv = x4[c];
            float4 pp = p4[c];
            t0 = fmaf(vv.x, pp.x, t0); t1 = fmaf(vv.y, pp.y, t1);
            t2 = fmaf(vv.z, pp.z, t2); t3 = fmaf(vv.w, pp.w, t3);
        }
        float vtp = (t0 + t1) + (t2 + t3);
        float Kc  = 0.5f * beta * vtp;
        float qi  = p - Kc * vi;               // 0 for lanes < m

        // A -= v q^T + q v^T  (q_j from smem on the fly; low reg pressure)
        #pragma unroll
        for (int c = 0; c < 8; c++) {
            float4 vv = x4[c];
            float4 pp = p4[c];
            float qx = fmaf(-Kc, vv.x, pp.x);
            float qy = fmaf(-Kc, vv.y, pp.y);
            float qz = fmaf(-Kc, vv.z, pp.z);
            float qw = fmaf(-Kc, vv.w, pp.w);
            a[4 * c + 0] = fmaf(-vi, qx, fmaf(-qi, vv.x, a[4 * c + 0]));
            a[4 * c + 1] = fmaf(-vi, qy, fmaf(-qi, vv.y, a[4 * c + 1]));
            a[4 * c + 2] = fmaf(-vi, qz, fmaf(-qi, vv.z, a[4 * c + 2]));
            a[4 * c + 3] = fmaf(-vi, qw, fmaf(-qi, vv.w, a[4 * c + 3]));
        }
        __syncwarp();   // xSh reused by next step's publish
    }
    {   // last offdiagonal e_30 = A[30][31]
        float e30 = __shfl_sync(FULLM, a[31], 30);
        if (lane == 0) {
            e2S[30] = e30 * e30; eaS[30] = fabsf(e30);
            e2S[31] = 0.f;       eaS[31] = 0.f;
        }
    }
    dS[lane] = sel32(a, lane);   // diagonal
    __syncwarp();

    // ================= multi-point Sturm bisection ==========================
    float eprev = (lane > 0) ? eaS[lane - 1] : 0.f;
    float rad   = eaS[lane] + eprev;
    float lo = wmin32(dS[lane] - rad);
    float hi = wmax32(dS[lane] + rad);

    // 3 targets x 10 lanes: ascending eigen indices 31 (e0), 24 (e7), 23 (e8).
    int g = lane / 10; if (g > 2) g = 2;
    const int mm = lane - g * 10;                // 0..9 (lanes 30,31 ignored)
    const int idx = (g == 0) ? 31 : (g == 1) ? 24 : 23;

    #pragma unroll 1
    for (int r = 0; r < 8; r++) {
        float w  = (hi - lo) * (1.0f / 11.0f);
        float xx = lo + w * (float)(mm + 1);
        int   cnt  = sturm32(dS, e2S, xx);
        unsigned bal = __ballot_sync(FULLM, cnt <= idx);
        unsigned gb  = (bal >> (g * 10)) & 0x3FFu;
        int mstar = 31 - __clz(gb);              // -1..9
        lo = lo + w * (float)(mstar + 1);
        hi = lo + w;
    }
    float lam = 0.5f * (lo + hi);
    float e0 = __shfl_sync(FULLM, lam, 0);
    float e7 = __shfl_sync(FULLM, lam, 10);
    float e8 = __shfl_sync(FULLM, lam, 20);

    if (lane == 0) {
        float gap   = e7 - e8;
        float decay = (e0 - e8) * (1.0f / 9.0f);
        float lmin  = e8 + 1e-8f;
        float topo  = gap / (decay + 1e-8f);
        if (topo < 0.f) topo = 0.f;
        float geo   = lmin / (traceSh + 1e-8f);
        float gcve  = topo + geo;
        out[b]         = gcve;   // gcve_scores
        out[n + b]     = 0.0f;   // fracture_scores
        out[2 * n + b] = gcve;   // total_pressure
    }
}

// ---------------------------------------------------------------------------
extern "C" void kernel_launch(void* const* d_in, const int* in_sizes, int n_in,
                              void* d_out, int out_size) {
    const float* h = (const float*)d_in[0];
    float* out = (float*)d_out;
    int n = out_size / 3;   // 32

    dim3 g1(NCH, BATCH);
    gram_kernel<<<g1, 544>>>(h);
    eig_kernel<<<148, 544>>>(out, n);   // blocks >= 32 exit immediately
}